// round 6
// baseline (speedup 1.0000x reference)
#include <cuda_runtime.h>
#include <cstdint>

#define HH 64
#define NN 512
#define BB 128
#define SCALE 0.125f

__device__ float g_qp[BB * NN * HH];
__device__ float g_kp[BB * NN * HH];
__device__ float g_vp[BB * NN * HH];

// ---------------- helpers ----------------
__device__ __forceinline__ uint32_t tf32r(float f) {
    uint32_t u;
    asm("cvt.rna.tf32.f32 %0, %1;" : "=r"(u) : "f"(f));
    return u;
}
__device__ __forceinline__ void mma_tf32(float* d, const uint32_t* a,
                                         uint32_t b0, uint32_t b1) {
    asm volatile(
        "mma.sync.aligned.m16n8k8.row.col.f32.tf32.tf32.f32 "
        "{%0,%1,%2,%3}, {%4,%5,%6,%7}, {%8,%9}, {%0,%1,%2,%3};"
        : "+f"(d[0]), "+f"(d[1]), "+f"(d[2]), "+f"(d[3])
        : "r"(a[0]), "r"(a[1]), "r"(a[2]), "r"(a[3]), "r"(b0), "r"(b1));
}
__device__ __forceinline__ void cpa16(uint32_t saddr, const void* gptr) {
    asm volatile("cp.async.cg.shared.global [%0], [%1], 16;" :: "r"(saddr), "l"(gptr));
}
__device__ __forceinline__ void cpa_commit() {
    asm volatile("cp.async.commit_group;" ::: "memory");
}
__device__ __forceinline__ void cpa_wait1() {
    asm volatile("cp.async.wait_group 1;" ::: "memory");
}

// ---------------------------------------------------------------------------
// Projection with tf32 mma; outputs stored tf32-pre-rounded.
// dst[b,n,k] = x[n,b,:] . W[k,:] + bias
// ---------------------------------------------------------------------------
__global__ __launch_bounds__(256, 2) void proj_kernel(
    const float* __restrict__ q, const float* __restrict__ k,
    const float* __restrict__ v,
    const float* __restrict__ Wq, const float* __restrict__ bq,
    const float* __restrict__ Wk, const float* __restrict__ bk,
    const float* __restrict__ Wv, const float* __restrict__ bv)
{
    __shared__ uint32_t sX[128 * 68];
    __shared__ uint32_t sW[64 * 68];
    __shared__ float    sB[64];

    const float* x; const float* W; const float* bias; float* dst;
    if (blockIdx.y == 0)      { x = q; W = Wq; bias = bq; dst = g_qp; }
    else if (blockIdx.y == 1) { x = k; W = Wk; bias = bk; dst = g_kp; }
    else                      { x = v; W = Wv; bias = bv; dst = g_vp; }

    const int tid  = threadIdx.x;
    const int row0 = blockIdx.x * 128;

    #pragma unroll
    for (int it = 0; it < 8; it++) {
        int idx = tid + it * 256;
        int r = idx >> 4, c4 = idx & 15;
        float4 t = *reinterpret_cast<const float4*>(x + (size_t)(row0 + r) * HH + c4 * 4);
        uint4 u = { tf32r(t.x), tf32r(t.y), tf32r(t.z), tf32r(t.w) };
        *reinterpret_cast<uint4*>(&sX[r * 68 + c4 * 4]) = u;
    }
    #pragma unroll
    for (int it = 0; it < 4; it++) {
        int idx = tid + it * 256;
        int r = idx >> 4, c4 = idx & 15;
        float4 t = *reinterpret_cast<const float4*>(W + (size_t)r * HH + c4 * 4);
        uint4 u = { tf32r(t.x), tf32r(t.y), tf32r(t.z), tf32r(t.w) };
        *reinterpret_cast<uint4*>(&sW[r * 68 + c4 * 4]) = u;
    }
    if (tid < 64) sB[tid] = bias[tid];
    __syncthreads();

    const int w    = tid >> 5;
    const int lane = tid & 31;
    const int lx   = lane & 3;
    const int ly   = lane >> 2;
    const int r0   = w * 16 + ly;
    const int r1   = r0 + 8;

    float acc[8][4];
    #pragma unroll
    for (int t = 0; t < 8; t++)
        #pragma unroll
        for (int i = 0; i < 4; i++) acc[t][i] = 0.f;

    #pragma unroll
    for (int k0 = 0; k0 < 64; k0 += 8) {
        uint32_t a[4];
        a[0] = sX[r0 * 68 + k0 + lx];
        a[1] = sX[r1 * 68 + k0 + lx];
        a[2] = sX[r0 * 68 + k0 + lx + 4];
        a[3] = sX[r1 * 68 + k0 + lx + 4];
        #pragma unroll
        for (int t = 0; t < 8; t++) {
            uint32_t b0 = sW[(t * 8 + ly) * 68 + k0 + lx];
            uint32_t b1 = sW[(t * 8 + ly) * 68 + k0 + 4 + lx];
            mma_tf32(acc[t], a, b0, b1);
        }
    }

    int g0 = row0 + r0, g1 = row0 + r1;
    float* orow0 = dst + ((size_t)(g0 & 127) * NN + (g0 >> 7)) * HH;
    float* orow1 = dst + ((size_t)(g1 & 127) * NN + (g1 >> 7)) * HH;
    #pragma unroll
    for (int t = 0; t < 8; t++) {
        int c0 = t * 8 + 2 * lx;
        float b0 = sB[c0], b1 = sB[c0 + 1];
        // store tf32-pre-rounded so attention can use raw frags
        float2 o0 = make_float2(__uint_as_float(tf32r(acc[t][0] + b0)),
                                __uint_as_float(tf32r(acc[t][1] + b1)));
        float2 o1 = make_float2(__uint_as_float(tf32r(acc[t][2] + b0)),
                                __uint_as_float(tf32r(acc[t][3] + b1)));
        *reinterpret_cast<float2*>(orow0 + c0) = o0;
        *reinterpret_cast<float2*>(orow1 + c0) = o1;
    }
}

// ---------------------------------------------------------------------------
// Attention, two-pass, no resident e-tile. CTA = 32 n-rows x one batch.
// Pass 1: rowsums of exp(S)*mask (K streamed). Pass 2: recompute S, write
// normalized A directly, stage one chunk of e, accumulate AV.
// 8 warps = 2 row-stripes x 4 quads. 3 CTAs/SM.
// ---------------------------------------------------------------------------
// smem float offsets
#define OQ   0                      // 32 x 68
#define OK0  2176                   // 32 x 68
#define OK1  4352                   // 32 x 68
#define OV0  6528                   // 32 x 72
#define OV1  8832                   // 32 x 72
#define OST  11136                  // 32 x 36 e-stage
#define OS   12288                  // 128 partial row sums
#define OI   12416                  // 32 inverse sums
#define SMEM_FLOATS 12448

__global__ __launch_bounds__(256, 3) void attn_kernel(
    const float* __restrict__ mask,
    float* __restrict__ out,     // [N,B,H]
    float* __restrict__ Aout)    // [B,N,N]
{
    extern __shared__ float sm[];
    uint32_t* sQu = reinterpret_cast<uint32_t*>(sm + OQ);
    uint32_t* sSt = reinterpret_cast<uint32_t*>(sm + OST);
    const uint32_t sbase = (uint32_t)__cvta_generic_to_shared(sm);

    const int tid  = threadIdx.x;
    const int w    = tid >> 5;
    const int lane = tid & 31;
    const int lx   = lane & 3;
    const int ly   = lane >> 2;
    const int stripe = w & 1;
    const int quad   = w >> 1;
    const int r0 = stripe * 16 + ly, r1 = r0 + 8;

    const int n0 = blockIdx.x * 32;
    const int b  = blockIdx.y;

    const float* qp = g_qp + (size_t)b * NN * HH;
    const float* kp = g_kp + (size_t)b * NN * HH;
    const float* vp = g_vp + (size_t)b * NN * HH;
    const float* mbase = mask + ((size_t)b * NN + n0) * NN;

    // ---- prologue: Q tile to smem (already tf32-rounded by proj)
    #pragma unroll
    for (int it = 0; it < 2; it++) {
        int idx = tid + it * 256;
        int r = idx >> 4, c4 = idx & 15;
        float4 t = *reinterpret_cast<const float4*>(qp + (size_t)(n0 + r) * HH + c4 * 4);
        *reinterpret_cast<float4*>(&sm[OQ + r * 68 + c4 * 4]) = t;
    }
    // prime K chunks 0,1
    #pragma unroll
    for (int it = 0; it < 2; it++) {
        int id = tid + it * 256;
        int r = id >> 4, c4 = id & 15;
        cpa16(sbase + (OK0 + r * 68 + c4 * 4) * 4, kp + (size_t)r * HH + c4 * 4);
    }
    cpa_commit();
    #pragma unroll
    for (int it = 0; it < 2; it++) {
        int id = tid + it * 256;
        int r = id >> 4, c4 = id & 15;
        cpa16(sbase + (OK1 + r * 68 + c4 * 4) * 4, kp + (size_t)(32 + r) * HH + c4 * 4);
    }
    cpa_commit();
    __syncthreads();

    const int colq = quad * 8 + 2 * lx;
    float2 mbuf[2][2];
    mbuf[0][0] = *reinterpret_cast<const float2*>(mbase + (size_t)r0 * NN + colq);
    mbuf[0][1] = *reinterpret_cast<const float2*>(mbase + (size_t)r1 * NN + colq);

    float rsum0 = 0.f, rsum1 = 0.f;

    // =============== pass 1: rowsums only ===============
    for (int c = 0; c < 16; c++) {
        const int p  = c & 1;
        const int OKp = p ? OK1 : OK0;
        uint32_t* sKu = reinterpret_cast<uint32_t*>(sm + OKp);

        cpa_wait1();
        __syncthreads();

        if (c + 1 < 16) {
            int gc = (c + 1) * 32 + colq;
            mbuf[(c + 1) & 1][0] = *reinterpret_cast<const float2*>(mbase + (size_t)r0 * NN + gc);
            mbuf[(c + 1) & 1][1] = *reinterpret_cast<const float2*>(mbase + (size_t)r1 * NN + gc);
        }

        float sacc[4] = {0.f, 0.f, 0.f, 0.f};
        #pragma unroll
        for (int kk = 0; kk < 8; kk++) {
            int k0 = kk * 8;
            uint32_t a[4];
            a[0] = sQu[r0 * 68 + k0 + lx];
            a[1] = sQu[r1 * 68 + k0 + lx];
            a[2] = sQu[r0 * 68 + k0 + lx + 4];
            a[3] = sQu[r1 * 68 + k0 + lx + 4];
            uint32_t b0 = sKu[(quad * 8 + ly) * 68 + k0 + lx];
            uint32_t b1 = sKu[(quad * 8 + ly) * 68 + k0 + 4 + lx];
            mma_tf32(sacc, a, b0, b1);
        }

        float2 m0 = mbuf[c & 1][0];
        float2 m1 = mbuf[c & 1][1];
        rsum0 += __expf(sacc[0] * SCALE) * m0.x + __expf(sacc[1] * SCALE) * m0.y;
        rsum1 += __expf(sacc[2] * SCALE) * m1.x + __expf(sacc[3] * SCALE) * m1.y;

        __syncthreads();     // all warps done with buffer p

        if (c + 2 < 16) {
            const int mt2 = (c + 2) * 32;
            #pragma unroll
            for (int it = 0; it < 2; it++) {
                int id = tid + it * 256;
                int r = id >> 4, c4 = id & 15;
                cpa16(sbase + (OKp + r * 68 + c4 * 4) * 4, kp + (size_t)(mt2 + r) * HH + c4 * 4);
            }
        }
        cpa_commit();
    }

    // ---- reduce rowsums -> inverse
    rsum0 += __shfl_xor_sync(0xffffffff, rsum0, 1);
    rsum0 += __shfl_xor_sync(0xffffffff, rsum0, 2);
    rsum1 += __shfl_xor_sync(0xffffffff, rsum1, 1);
    rsum1 += __shfl_xor_sync(0xffffffff, rsum1, 2);
    if (lx == 0) {
        sm[OS + quad * 32 + r0] = rsum0;
        sm[OS + quad * 32 + r1] = rsum1;
    }
    __syncthreads();
    if (tid < 32) {
        float s = sm[OS + tid] + sm[OS + 32 + tid] + sm[OS + 64 + tid] + sm[OS + 96 + tid];
        sm[OI + tid] = (s == 0.f) ? 1.f : (1.f / s);
    }
    __syncthreads();
    const float i0 = sm[OI + r0];
    const float i1 = sm[OI + r1];

    // =============== pass 2: recompute, write A, AV ===============
    // prime K0+V0, K1+V1
    #pragma unroll
    for (int it = 0; it < 2; it++) {
        int id = tid + it * 256;
        int r = id >> 4, c4 = id & 15;
        cpa16(sbase + (OK0 + r * 68 + c4 * 4) * 4, kp + (size_t)r * HH + c4 * 4);
        cpa16(sbase + (OV0 + r * 72 + c4 * 4) * 4, vp + (size_t)r * HH + c4 * 4);
    }
    cpa_commit();
    #pragma unroll
    for (int it = 0; it < 2; it++) {
        int id = tid + it * 256;
        int r = id >> 4, c4 = id & 15;
        cpa16(sbase + (OK1 + r * 68 + c4 * 4) * 4, kp + (size_t)(32 + r) * HH + c4 * 4);
        cpa16(sbase + (OV1 + r * 72 + c4 * 4) * 4, vp + (size_t)(32 + r) * HH + c4 * 4);
    }
    cpa_commit();

    mbuf[0][0] = *reinterpret_cast<const float2*>(mbase + (size_t)r0 * NN + colq);
    mbuf[0][1] = *reinterpret_cast<const float2*>(mbase + (size_t)r1 * NN + colq);

    float* Arow0 = Aout + ((size_t)b * NN + n0 + r0) * NN;
    float* Arow1 = Aout + ((size_t)b * NN + n0 + r1) * NN;

    float oacc[2][4];
    #pragma unroll
    for (int t = 0; t < 2; t++)
        #pragma unroll
        for (int i = 0; i < 4; i++) oacc[t][i] = 0.f;

    for (int c = 0; c < 16; c++) {
        const int p  = c & 1;
        const int mt = c * 32;
        const int OKp = p ? OK1 : OK0;
        const int OVp = p ? OV1 : OV0;
        uint32_t* sKu = reinterpret_cast<uint32_t*>(sm + OKp);
        uint32_t* sVu = reinterpret_cast<uint32_t*>(sm + OVp);

        cpa_wait1();
        __syncthreads();          // K/V(c) visible; stage free

        if (c + 1 < 16) {
            int gc = (c + 1) * 32 + colq;
            mbuf[(c + 1) & 1][0] = *reinterpret_cast<const float2*>(mbase + (size_t)r0 * NN + gc);
            mbuf[(c + 1) & 1][1] = *reinterpret_cast<const float2*>(mbase + (size_t)r1 * NN + gc);
        }

        float sacc[4] = {0.f, 0.f, 0.f, 0.f};
        #pragma unroll
        for (int kk = 0; kk < 8; kk++) {
            int k0 = kk * 8;
            uint32_t a[4];
            a[0] = sQu[r0 * 68 + k0 + lx];
            a[1] = sQu[r1 * 68 + k0 + lx];
            a[2] = sQu[r0 * 68 + k0 + lx + 4];
            a[3] = sQu[r1 * 68 + k0 + lx + 4];
            uint32_t b0 = sKu[(quad * 8 + ly) * 68 + k0 + lx];
            uint32_t b1 = sKu[(quad * 8 + ly) * 68 + k0 + 4 + lx];
            mma_tf32(sacc, a, b0, b1);
        }

        {
            float2 m0 = mbuf[c & 1][0];
            float2 m1 = mbuf[c & 1][1];
            float a00 = __expf(sacc[0] * SCALE) * m0.x * i0;
            float a01 = __expf(sacc[1] * SCALE) * m0.y * i0;
            float a10 = __expf(sacc[2] * SCALE) * m1.x * i1;
            float a11 = __expf(sacc[3] * SCALE) * m1.y * i1;
            // write A (normalized) directly
            *reinterpret_cast<float2*>(Arow0 + mt + colq) = make_float2(a00, a01);
            *reinterpret_cast<float2*>(Arow1 + mt + colq) = make_float2(a10, a11);
            // stage tf32-rounded normalized e for AV
            sSt[r0 * 36 + colq]     = tf32r(a00);
            sSt[r0 * 36 + colq + 1] = tf32r(a01);
            sSt[r1 * 36 + colq]     = tf32r(a10);
            sSt[r1 * 36 + colq + 1] = tf32r(a11);
        }
        __syncthreads();          // stage visible

        #pragma unroll
        for (int k0 = 0; k0 < 32; k0 += 8) {
            uint32_t a[4];
            a[0] = sSt[r0 * 36 + k0 + lx];
            a[1] = sSt[r1 * 36 + k0 + lx];
            a[2] = sSt[r0 * 36 + k0 + lx + 4];
            a[3] = sSt[r1 * 36 + k0 + lx + 4];
            #pragma unroll
            for (int t = 0; t < 2; t++) {
                int h = quad * 16 + t * 8 + ly;
                uint32_t b0 = sVu[(k0 + lx) * 72 + h];
                uint32_t b1 = sVu[(k0 + 4 + lx) * 72 + h];
                mma_tf32(oacc[t], a, b0, b1);
            }
        }
        __syncthreads();          // K/V/stage reusable

        if (c + 2 < 16) {
            const int mt2 = (c + 2) * 32;
            #pragma unroll
            for (int it = 0; it < 2; it++) {
                int id = tid + it * 256;
                int r = id >> 4, c4 = id & 15;
                cpa16(sbase + (OKp + r * 68 + c4 * 4) * 4, kp + (size_t)(mt2 + r) * HH + c4 * 4);
                cpa16(sbase + (OVp + r * 72 + c4 * 4) * 4, vp + (size_t)(mt2 + r) * HH + c4 * 4);
            }
        }
        cpa_commit();
    }

    // ---- epilogue: out (oacc already normalized) via smem staging
    {
        float* sO = sm + OK0;   // 32 x 68
        #pragma unroll
        for (int t = 0; t < 2; t++) {
            int h = quad * 16 + t * 8 + 2 * lx;
            *reinterpret_cast<float2*>(&sO[r0 * 68 + h]) = make_float2(oacc[t][0], oacc[t][1]);
            *reinterpret_cast<float2*>(&sO[r1 * 68 + h]) = make_float2(oacc[t][2], oacc[t][3]);
        }
        __syncthreads();
        #pragma unroll
        for (int it = 0; it < 2; it++) {
            int idx = tid + it * 256;
            int row = idx >> 4, c4 = idx & 15;
            float4 t = *reinterpret_cast<const float4*>(&sO[row * 68 + 4 * c4]);
            *reinterpret_cast<float4*>(out + ((size_t)(n0 + row) * BB + b) * HH + 4 * c4) = t;
        }
    }
}

// ---------------------------------------------------------------------------
extern "C" void kernel_launch(void* const* d_in, const int* in_sizes, int n_in,
                              void* d_out, int out_size)
{
    const float* q    = (const float*)d_in[0];
    const float* k    = (const float*)d_in[1];
    const float* v    = (const float*)d_in[2];
    const float* mask = (const float*)d_in[3];
    const float* Wq   = (const float*)d_in[4];
    const float* bq   = (const float*)d_in[5];
    const float* Wk   = (const float*)d_in[6];
    const float* bk   = (const float*)d_in[7];
    const float* Wv   = (const float*)d_in[8];
    const float* bv   = (const float*)d_in[9];

    float* out  = (float*)d_out;                         // [N,B,H] first
    float* Aout = (float*)d_out + (size_t)NN * BB * HH;  // then [B,N,N]

    const int smem_bytes = SMEM_FLOATS * 4;
    cudaFuncSetAttribute(attn_kernel, cudaFuncAttributeMaxDynamicSharedMemorySize,
                         smem_bytes);

    proj_kernel<<<dim3((NN * BB) / 128, 3), 256>>>(q, k, v, Wq, bq, Wk, bk, Wv, bv);
    attn_kernel<<<dim3(NN / 32, BB), 256, smem_bytes>>>(mask, out, Aout);
}

// round 7
// speedup vs baseline: 1.4627x; 1.4627x over previous
#include <cuda_runtime.h>
#include <cstdint>

#define HH 64
#define NN 512
#define BB 128
#define SCALE 0.125f

__device__ float g_qp[BB * NN * HH];
__device__ float g_kp[BB * NN * HH];
__device__ float g_vp[BB * NN * HH];

// ---------------- helpers ----------------
__device__ __forceinline__ uint32_t tf32r(float f) {
    uint32_t u;
    asm("cvt.rna.tf32.f32 %0, %1;" : "=r"(u) : "f"(f));
    return u;
}
__device__ __forceinline__ void mma_tf32(float* d, const uint32_t* a,
                                         uint32_t b0, uint32_t b1) {
    asm volatile(
        "mma.sync.aligned.m16n8k8.row.col.f32.tf32.tf32.f32 "
        "{%0,%1,%2,%3}, {%4,%5,%6,%7}, {%8,%9}, {%0,%1,%2,%3};"
        : "+f"(d[0]), "+f"(d[1]), "+f"(d[2]), "+f"(d[3])
        : "r"(a[0]), "r"(a[1]), "r"(a[2]), "r"(a[3]), "r"(b0), "r"(b1));
}

// ---------------------------------------------------------------------------
// Projection with tf32 mma; outputs stored tf32-pre-rounded (rna).
// dst[b,n,k] = x[n,b,:] . W[k,:] + bias
// ---------------------------------------------------------------------------
__global__ __launch_bounds__(256, 2) void proj_kernel(
    const float* __restrict__ q, const float* __restrict__ k,
    const float* __restrict__ v,
    const float* __restrict__ Wq, const float* __restrict__ bq,
    const float* __restrict__ Wk, const float* __restrict__ bk,
    const float* __restrict__ Wv, const float* __restrict__ bv)
{
    __shared__ uint32_t sX[128 * 68];
    __shared__ uint32_t sW[64 * 68];
    __shared__ float    sB[64];

    const float* x; const float* W; const float* bias; float* dst;
    if (blockIdx.y == 0)      { x = q; W = Wq; bias = bq; dst = g_qp; }
    else if (blockIdx.y == 1) { x = k; W = Wk; bias = bk; dst = g_kp; }
    else                      { x = v; W = Wv; bias = bv; dst = g_vp; }

    const int tid  = threadIdx.x;
    const int row0 = blockIdx.x * 128;

    #pragma unroll
    for (int it = 0; it < 8; it++) {
        int idx = tid + it * 256;
        int r = idx >> 4, c4 = idx & 15;
        float4 t = *reinterpret_cast<const float4*>(x + (size_t)(row0 + r) * HH + c4 * 4);
        uint4 u = { tf32r(t.x), tf32r(t.y), tf32r(t.z), tf32r(t.w) };
        *reinterpret_cast<uint4*>(&sX[r * 68 + c4 * 4]) = u;
    }
    #pragma unroll
    for (int it = 0; it < 4; it++) {
        int idx = tid + it * 256;
        int r = idx >> 4, c4 = idx & 15;
        float4 t = *reinterpret_cast<const float4*>(W + (size_t)r * HH + c4 * 4);
        uint4 u = { tf32r(t.x), tf32r(t.y), tf32r(t.z), tf32r(t.w) };
        *reinterpret_cast<uint4*>(&sW[r * 68 + c4 * 4]) = u;
    }
    if (tid < 64) sB[tid] = bias[tid];
    __syncthreads();

    const int w    = tid >> 5;
    const int lane = tid & 31;
    const int lx   = lane & 3;
    const int ly   = lane >> 2;
    const int r0   = w * 16 + ly;
    const int r1   = r0 + 8;

    float acc[8][4];
    #pragma unroll
    for (int t = 0; t < 8; t++)
        #pragma unroll
        for (int i = 0; i < 4; i++) acc[t][i] = 0.f;

    #pragma unroll
    for (int k0 = 0; k0 < 64; k0 += 8) {
        uint32_t a[4];
        a[0] = sX[r0 * 68 + k0 + lx];
        a[1] = sX[r1 * 68 + k0 + lx];
        a[2] = sX[r0 * 68 + k0 + lx + 4];
        a[3] = sX[r1 * 68 + k0 + lx + 4];
        #pragma unroll
        for (int t = 0; t < 8; t++) {
            uint32_t b0 = sW[(t * 8 + ly) * 68 + k0 + lx];
            uint32_t b1 = sW[(t * 8 + ly) * 68 + k0 + 4 + lx];
            mma_tf32(acc[t], a, b0, b1);
        }
    }

    int g0 = row0 + r0, g1 = row0 + r1;
    float* orow0 = dst + ((size_t)(g0 & 127) * NN + (g0 >> 7)) * HH;
    float* orow1 = dst + ((size_t)(g1 & 127) * NN + (g1 >> 7)) * HH;
    #pragma unroll
    for (int t = 0; t < 8; t++) {
        int c0 = t * 8 + 2 * lx;
        float b0 = sB[c0], b1 = sB[c0 + 1];
        float2 o0 = make_float2(__uint_as_float(tf32r(acc[t][0] + b0)),
                                __uint_as_float(tf32r(acc[t][1] + b1)));
        float2 o1 = make_float2(__uint_as_float(tf32r(acc[t][2] + b0)),
                                __uint_as_float(tf32r(acc[t][3] + b1)));
        *reinterpret_cast<float2*>(orow0 + c0) = o0;
        *reinterpret_cast<float2*>(orow1 + c0) = o1;
    }
}

// ---------------------------------------------------------------------------
// Attention: CTA = 64 n-rows x one batch, 512 threads (16 warps =
// 4 row-stripes x 4 col-quads), 4 chunks of 128 keys, full e-tile in smem.
// ---------------------------------------------------------------------------
// smem float offsets
#define OQ   0                      // 64 x 68
#define OK_  4352                   // 128 x 68
#define OV   13056                  // 128 x 72
#define OA   22272                  // 64 x 516
#define OS   55296                  // 256 partial row sums (4 quads x 64)
#define OI   55552                  // 64 inverse sums
#define SMEM_FLOATS 55616

__global__ __launch_bounds__(512, 1) void attn_kernel(
    const float* __restrict__ mask,
    float* __restrict__ out,     // [N,B,H]
    float* __restrict__ Aout)    // [B,N,N]
{
    extern __shared__ float sm[];
    float*    sAf = sm + OA;
    uint32_t* sQu = reinterpret_cast<uint32_t*>(sm + OQ);
    uint32_t* sKu = reinterpret_cast<uint32_t*>(sm + OK_);
    uint32_t* sVu = reinterpret_cast<uint32_t*>(sm + OV);
    uint32_t* sAu = reinterpret_cast<uint32_t*>(sm + OA);

    const int tid  = threadIdx.x;
    const int w    = tid >> 5;
    const int lane = tid & 31;
    const int lx   = lane & 3;
    const int ly   = lane >> 2;
    const int stripe = w & 3;        // 16-row stripe (0..3)
    const int quad   = w >> 2;       // column group (0..3)
    const int r0 = stripe * 16 + ly, r1 = r0 + 8;

    const int n0 = blockIdx.x * 64;
    const int b  = blockIdx.y;

    const float* qp = g_qp + (size_t)b * NN * HH;
    const float* kp = g_kp + (size_t)b * NN * HH;
    const float* vp = g_vp + (size_t)b * NN * HH;
    const float* mbase = mask + ((size_t)b * NN + n0) * NN;

    // ---- Q tile (64 x 64), already tf32-rounded by proj
    #pragma unroll
    for (int it = 0; it < 2; it++) {
        int idx = tid + it * 512;
        int r = idx >> 4, c4 = idx & 15;
        float4 t = *reinterpret_cast<const float4*>(qp + (size_t)(n0 + r) * HH + c4 * 4);
        *reinterpret_cast<float4*>(&sm[OQ + r * 68 + c4 * 4]) = t;
    }
    __syncthreads();

    // ---- Q fragments hoisted (held whole kernel)
    uint32_t qf[8][4];
    #pragma unroll
    for (int kk = 0; kk < 8; kk++) {
        int k0 = kk * 8;
        qf[kk][0] = sQu[r0 * 68 + k0 + lx];
        qf[kk][1] = sQu[r1 * 68 + k0 + lx];
        qf[kk][2] = sQu[r0 * 68 + k0 + lx + 4];
        qf[kk][3] = sQu[r1 * 68 + k0 + lx + 4];
    }

    float oacc[2][4];
    #pragma unroll
    for (int t = 0; t < 2; t++)
        #pragma unroll
        for (int i = 0; i < 4; i++) oacc[t][i] = 0.f;
    float rsum0 = 0.f, rsum1 = 0.f;

    for (int c = 0; c < 4; c++) {
        const int mt = c * 128;
        __syncthreads();   // prev AV done with sK/sV

        // ---- load K/V chunk (128 x 64 each), raw copies (pre-rounded)
        #pragma unroll
        for (int it = 0; it < 4; it++) {
            int idx = tid + it * 512;
            int r = idx >> 4, c4 = idx & 15;
            float4 t = *reinterpret_cast<const float4*>(kp + (size_t)(mt + r) * HH + c4 * 4);
            *reinterpret_cast<float4*>(&sm[OK_ + r * 68 + c4 * 4]) = t;
            float4 s = *reinterpret_cast<const float4*>(vp + (size_t)(mt + r) * HH + c4 * 4);
            *reinterpret_cast<float4*>(&sm[OV + r * 72 + c4 * 4]) = s;
        }
        __syncthreads();

        // ---- issue mask loads early (latency covered by S-MMA below)
        float2 m0[4], m1[4];
        #pragma unroll
        for (int t = 0; t < 4; t++) {
            int gc = mt + quad * 32 + t * 8 + 2 * lx;
            m0[t] = *reinterpret_cast<const float2*>(mbase + (size_t)r0 * NN + gc);
            m1[t] = *reinterpret_cast<const float2*>(mbase + (size_t)r1 * NN + gc);
        }

        // ---- S = Q K^T : 16 rows x 32 keys per warp
        float sacc[4][4];
        #pragma unroll
        for (int t = 0; t < 4; t++)
            #pragma unroll
            for (int i = 0; i < 4; i++) sacc[t][i] = 0.f;

        #pragma unroll
        for (int kk = 0; kk < 8; kk++) {
            int k0 = kk * 8;
            #pragma unroll
            for (int t = 0; t < 4; t++) {
                int key = quad * 32 + t * 8 + ly;
                uint32_t b0 = sKu[key * 68 + k0 + lx];
                uint32_t b1 = sKu[key * 68 + k0 + 4 + lx];
                mma_tf32(sacc[t], qf[kk], b0, b1);
            }
        }

        // ---- e = exp(S/8)*mask ; rowsums ; stage into sA (tf32 rna)
        #pragma unroll
        for (int t = 0; t < 4; t++) {
            int gc = mt + quad * 32 + t * 8 + 2 * lx;
            float e00 = __uint_as_float(tf32r(__expf(sacc[t][0] * SCALE) * m0[t].x));
            float e01 = __uint_as_float(tf32r(__expf(sacc[t][1] * SCALE) * m0[t].y));
            float e10 = __uint_as_float(tf32r(__expf(sacc[t][2] * SCALE) * m1[t].x));
            float e11 = __uint_as_float(tf32r(__expf(sacc[t][3] * SCALE) * m1[t].y));
            rsum0 += e00 + e01;
            rsum1 += e10 + e11;
            *reinterpret_cast<float2*>(&sAf[r0 * 516 + gc]) = make_float2(e00, e01);
            *reinterpret_cast<float2*>(&sAf[r1 * 516 + gc]) = make_float2(e10, e11);
        }
        __syncthreads();   // e visible to all warps

        // ---- AV accumulate: 16 rows x 16 h-cols per warp, k over 128 keys
        #pragma unroll
        for (int k0 = 0; k0 < 128; k0 += 8) {
            uint32_t a[4];
            a[0] = sAu[r0 * 516 + mt + k0 + lx];
            a[1] = sAu[r1 * 516 + mt + k0 + lx];
            a[2] = sAu[r0 * 516 + mt + k0 + lx + 4];
            a[3] = sAu[r1 * 516 + mt + k0 + lx + 4];
            #pragma unroll
            for (int t = 0; t < 2; t++) {
                int h = quad * 16 + t * 8 + ly;
                uint32_t b0 = sVu[(k0 + lx) * 72 + h];
                uint32_t b1 = sVu[(k0 + 4 + lx) * 72 + h];
                mma_tf32(oacc[t], a, b0, b1);
            }
        }
    }

    // ---- row sums -> inverse
    rsum0 += __shfl_xor_sync(0xffffffff, rsum0, 1);
    rsum0 += __shfl_xor_sync(0xffffffff, rsum0, 2);
    rsum1 += __shfl_xor_sync(0xffffffff, rsum1, 1);
    rsum1 += __shfl_xor_sync(0xffffffff, rsum1, 2);
    if (lx == 0) {
        sm[OS + quad * 64 + r0] = rsum0;
        sm[OS + quad * 64 + r1] = rsum1;
    }
    __syncthreads();
    if (tid < 64) {
        float s = sm[OS + tid] + sm[OS + 64 + tid] + sm[OS + 128 + tid] + sm[OS + 192 + tid];
        sm[OI + tid] = (s == 0.f) ? 1.f : (1.f / s);
    }
    __syncthreads();

    // ---- write normalized A (coalesced float4)
    {
        int row = tid >> 3, s8 = tid & 7;
        float inv = sm[OI + row];
        float4* grow = reinterpret_cast<float4*>(Aout + ((size_t)b * NN + n0 + row) * NN);
        #pragma unroll
        for (int i = 0; i < 16; i++) {
            int c4 = s8 + 8 * i;
            float4 t = *reinterpret_cast<const float4*>(&sAf[row * 516 + 4 * c4]);
            t.x *= inv; t.y *= inv; t.z *= inv; t.w *= inv;
            grow[c4] = t;
        }
    }

    // ---- stage out through smem (reuse sK region), coalesced write
    {
        float* sO = sm + OK_;   // 64 x 68 fits in sK region
        float i0 = sm[OI + r0], i1 = sm[OI + r1];
        #pragma unroll
        for (int t = 0; t < 2; t++) {
            int h = quad * 16 + t * 8 + 2 * lx;
            *reinterpret_cast<float2*>(&sO[r0 * 68 + h]) =
                make_float2(oacc[t][0] * i0, oacc[t][1] * i0);
            *reinterpret_cast<float2*>(&sO[r1 * 68 + h]) =
                make_float2(oacc[t][2] * i1, oacc[t][3] * i1);
        }
        __syncthreads();
        #pragma unroll
        for (int it = 0; it < 2; it++) {
            int idx = tid + it * 512;
            int row = idx >> 4, c4 = idx & 15;
            float4 t = *reinterpret_cast<const float4*>(&sO[row * 68 + 4 * c4]);
            *reinterpret_cast<float4*>(out + ((size_t)(n0 + row) * BB + b) * HH + 4 * c4) = t;
        }
    }
}

// ---------------------------------------------------------------------------
extern "C" void kernel_launch(void* const* d_in, const int* in_sizes, int n_in,
                              void* d_out, int out_size)
{
    const float* q    = (const float*)d_in[0];
    const float* k    = (const float*)d_in[1];
    const float* v    = (const float*)d_in[2];
    const float* mask = (const float*)d_in[3];
    const float* Wq   = (const float*)d_in[4];
    const float* bq   = (const float*)d_in[5];
    const float* Wk   = (const float*)d_in[6];
    const float* bk   = (const float*)d_in[7];
    const float* Wv   = (const float*)d_in[8];
    const float* bv   = (const float*)d_in[9];

    float* out  = (float*)d_out;                         // [N,B,H] first
    float* Aout = (float*)d_out + (size_t)NN * BB * HH;  // then [B,N,N]

    const int smem_bytes = SMEM_FLOATS * 4;
    cudaFuncSetAttribute(attn_kernel, cudaFuncAttributeMaxDynamicSharedMemorySize,
                         smem_bytes);

    proj_kernel<<<dim3((NN * BB) / 128, 3), 256>>>(q, k, v, Wq, bq, Wk, bk, Wv, bv);
    attn_kernel<<<dim3(NN / 64, BB), 512, smem_bytes>>>(mask, out, Aout);
}

// round 8
// speedup vs baseline: 1.4776x; 1.0102x over previous
#include <cuda_runtime.h>
#include <cstdint>

#define HH 64
#define NN 512
#define BB 128
#define SCALE 0.125f

__device__ float g_qp[BB * NN * HH];
__device__ float g_kp[BB * NN * HH];
__device__ float g_vp[BB * NN * HH];

// ---------------- helpers ----------------
__device__ __forceinline__ uint32_t tf32r(float f) {
    uint32_t u;
    asm("cvt.rna.tf32.f32 %0, %1;" : "=r"(u) : "f"(f));
    return u;
}
__device__ __forceinline__ void mma_tf32(float* d, const uint32_t* a,
                                         uint32_t b0, uint32_t b1) {
    asm volatile(
        "mma.sync.aligned.m16n8k8.row.col.f32.tf32.tf32.f32 "
        "{%0,%1,%2,%3}, {%4,%5,%6,%7}, {%8,%9}, {%0,%1,%2,%3};"
        : "+f"(d[0]), "+f"(d[1]), "+f"(d[2]), "+f"(d[3])
        : "r"(a[0]), "r"(a[1]), "r"(a[2]), "r"(a[3]), "r"(b0), "r"(b1));
}

// exp(s * 0.125) computed entirely on FMA/ALU pipes (no MUFU, no F2I/I2F).
// y = s*0.125*log2(e); round via magic-number; 2^f by degree-5 Taylor on [-0.5,0.5].
__device__ __forceinline__ float fexp8(float s) {
    float y = s * 0.18033688011112042f;      // 0.125 * log2(e)
    float z = y + 12582912.0f;               // 1.5 * 2^23 : RN to integer
    int   i = __float_as_int(z) - 0x4B400000;
    float f = y - (z - 12582912.0f);         // f in [-0.5, 0.5]
    float p = 0.0013333558f;
    p = p * f + 0.0096181291f;
    p = p * f + 0.0555041087f;
    p = p * f + 0.2402265070f;
    p = p * f + 0.6931471806f;
    p = p * f + 1.0f;
    return __int_as_float(__float_as_int(p) + (i << 23));
}

// ---------------------------------------------------------------------------
// Projection with tf32 mma; outputs stored tf32-pre-rounded (rna).
// dst[b,n,k] = x[n,b,:] . W[k,:] + bias
// ---------------------------------------------------------------------------
__global__ __launch_bounds__(256, 2) void proj_kernel(
    const float* __restrict__ q, const float* __restrict__ k,
    const float* __restrict__ v,
    const float* __restrict__ Wq, const float* __restrict__ bq,
    const float* __restrict__ Wk, const float* __restrict__ bk,
    const float* __restrict__ Wv, const float* __restrict__ bv)
{
    __shared__ uint32_t sX[128 * 68];
    __shared__ uint32_t sW[64 * 68];
    __shared__ float    sB[64];

    const float* x; const float* W; const float* bias; float* dst;
    if (blockIdx.y == 0)      { x = q; W = Wq; bias = bq; dst = g_qp; }
    else if (blockIdx.y == 1) { x = k; W = Wk; bias = bk; dst = g_kp; }
    else                      { x = v; W = Wv; bias = bv; dst = g_vp; }

    const int tid  = threadIdx.x;
    const int row0 = blockIdx.x * 128;

    #pragma unroll
    for (int it = 0; it < 8; it++) {
        int idx = tid + it * 256;
        int r = idx >> 4, c4 = idx & 15;
        float4 t = *reinterpret_cast<const float4*>(x + (size_t)(row0 + r) * HH + c4 * 4);
        uint4 u = { tf32r(t.x), tf32r(t.y), tf32r(t.z), tf32r(t.w) };
        *reinterpret_cast<uint4*>(&sX[r * 68 + c4 * 4]) = u;
    }
    #pragma unroll
    for (int it = 0; it < 4; it++) {
        int idx = tid + it * 256;
        int r = idx >> 4, c4 = idx & 15;
        float4 t = *reinterpret_cast<const float4*>(W + (size_t)r * HH + c4 * 4);
        uint4 u = { tf32r(t.x), tf32r(t.y), tf32r(t.z), tf32r(t.w) };
        *reinterpret_cast<uint4*>(&sW[r * 68 + c4 * 4]) = u;
    }
    if (tid < 64) sB[tid] = bias[tid];
    __syncthreads();

    const int w    = tid >> 5;
    const int lane = tid & 31;
    const int lx   = lane & 3;
    const int ly   = lane >> 2;
    const int r0   = w * 16 + ly;
    const int r1   = r0 + 8;

    float acc[8][4];
    #pragma unroll
    for (int t = 0; t < 8; t++)
        #pragma unroll
        for (int i = 0; i < 4; i++) acc[t][i] = 0.f;

    #pragma unroll
    for (int k0 = 0; k0 < 64; k0 += 8) {
        uint32_t a[4];
        a[0] = sX[r0 * 68 + k0 + lx];
        a[1] = sX[r1 * 68 + k0 + lx];
        a[2] = sX[r0 * 68 + k0 + lx + 4];
        a[3] = sX[r1 * 68 + k0 + lx + 4];
        #pragma unroll
        for (int t = 0; t < 8; t++) {
            uint32_t b0 = sW[(t * 8 + ly) * 68 + k0 + lx];
            uint32_t b1 = sW[(t * 8 + ly) * 68 + k0 + 4 + lx];
            mma_tf32(acc[t], a, b0, b1);
        }
    }

    int g0 = row0 + r0, g1 = row0 + r1;
    float* orow0 = dst + ((size_t)(g0 & 127) * NN + (g0 >> 7)) * HH;
    float* orow1 = dst + ((size_t)(g1 & 127) * NN + (g1 >> 7)) * HH;
    #pragma unroll
    for (int t = 0; t < 8; t++) {
        int c0 = t * 8 + 2 * lx;
        float b0 = sB[c0], b1 = sB[c0 + 1];
        float2 o0 = make_float2(__uint_as_float(tf32r(acc[t][0] + b0)),
                                __uint_as_float(tf32r(acc[t][1] + b1)));
        float2 o1 = make_float2(__uint_as_float(tf32r(acc[t][2] + b0)),
                                __uint_as_float(tf32r(acc[t][3] + b1)));
        *reinterpret_cast<float2*>(orow0 + c0) = o0;
        *reinterpret_cast<float2*>(orow1 + c0) = o1;
    }
}

// ---------------------------------------------------------------------------
// Attention: CTA = 64 n-rows x one batch, 512 threads (16 warps =
// 4 row-stripes x 4 col-quads), 4 chunks of 128 keys, full e-tile in smem.
// ---------------------------------------------------------------------------
// smem float offsets
#define OQ   0                      // 64 x 68
#define OK_  4352                   // 128 x 68
#define OV   13056                  // 128 x 72
#define OA   22272                  // 64 x 516
#define OS   55296                  // 256 partial row sums (4 quads x 64)
#define OI   55552                  // 64 inverse sums
#define SMEM_FLOATS 55616

__global__ __launch_bounds__(512, 1) void attn_kernel(
    const float* __restrict__ mask,
    float* __restrict__ out,     // [N,B,H]
    float* __restrict__ Aout)    // [B,N,N]
{
    extern __shared__ float sm[];
    float*    sAf = sm + OA;
    uint32_t* sQu = reinterpret_cast<uint32_t*>(sm + OQ);
    uint32_t* sKu = reinterpret_cast<uint32_t*>(sm + OK_);
    uint32_t* sVu = reinterpret_cast<uint32_t*>(sm + OV);
    uint32_t* sAu = reinterpret_cast<uint32_t*>(sm + OA);

    const int tid  = threadIdx.x;
    const int w    = tid >> 5;
    const int lane = tid & 31;
    const int lx   = lane & 3;
    const int ly   = lane >> 2;
    const int stripe = w & 3;        // 16-row stripe (0..3)
    const int quad   = w >> 2;       // column group (0..3)
    const int r0 = stripe * 16 + ly, r1 = r0 + 8;

    const int n0 = blockIdx.x * 64;
    const int b  = blockIdx.y;

    const float* qp = g_qp + (size_t)b * NN * HH;
    const float* kp = g_kp + (size_t)b * NN * HH;
    const float* vp = g_vp + (size_t)b * NN * HH;
    const float* mbase = mask + ((size_t)b * NN + n0) * NN;

    // ---- Q tile (64 x 64), already tf32-rounded by proj
    #pragma unroll
    for (int it = 0; it < 2; it++) {
        int idx = tid + it * 512;
        int r = idx >> 4, c4 = idx & 15;
        float4 t = *reinterpret_cast<const float4*>(qp + (size_t)(n0 + r) * HH + c4 * 4);
        *reinterpret_cast<float4*>(&sm[OQ + r * 68 + c4 * 4]) = t;
    }
    __syncthreads();

    // ---- Q fragments hoisted (held whole kernel)
    uint32_t qf[8][4];
    #pragma unroll
    for (int kk = 0; kk < 8; kk++) {
        int k0 = kk * 8;
        qf[kk][0] = sQu[r0 * 68 + k0 + lx];
        qf[kk][1] = sQu[r1 * 68 + k0 + lx];
        qf[kk][2] = sQu[r0 * 68 + k0 + lx + 4];
        qf[kk][3] = sQu[r1 * 68 + k0 + lx + 4];
    }

    float oacc[2][4];
    #pragma unroll
    for (int t = 0; t < 2; t++)
        #pragma unroll
        for (int i = 0; i < 4; i++) oacc[t][i] = 0.f;
    float rsum0 = 0.f, rsum1 = 0.f;

    for (int c = 0; c < 4; c++) {
        const int mt = c * 128;
        __syncthreads();   // prev AV done with sK/sV

        // ---- load K/V chunk (128 x 64 each), raw copies (pre-rounded)
        #pragma unroll
        for (int it = 0; it < 4; it++) {
            int idx = tid + it * 512;
            int r = idx >> 4, c4 = idx & 15;
            float4 t = *reinterpret_cast<const float4*>(kp + (size_t)(mt + r) * HH + c4 * 4);
            *reinterpret_cast<float4*>(&sm[OK_ + r * 68 + c4 * 4]) = t;
            float4 s = *reinterpret_cast<const float4*>(vp + (size_t)(mt + r) * HH + c4 * 4);
            *reinterpret_cast<float4*>(&sm[OV + r * 72 + c4 * 4]) = s;
        }
        __syncthreads();

        // ---- issue mask loads early (latency covered by S-MMA below)
        float2 m0[4], m1[4];
        #pragma unroll
        for (int t = 0; t < 4; t++) {
            int gc = mt + quad * 32 + t * 8 + 2 * lx;
            m0[t] = *reinterpret_cast<const float2*>(mbase + (size_t)r0 * NN + gc);
            m1[t] = *reinterpret_cast<const float2*>(mbase + (size_t)r1 * NN + gc);
        }

        // ---- S = Q K^T : 16 rows x 32 keys per warp
        float sacc[4][4];
        #pragma unroll
        for (int t = 0; t < 4; t++)
            #pragma unroll
            for (int i = 0; i < 4; i++) sacc[t][i] = 0.f;

        #pragma unroll
        for (int kk = 0; kk < 8; kk++) {
            int k0 = kk * 8;
            #pragma unroll
            for (int t = 0; t < 4; t++) {
                int key = quad * 32 + t * 8 + ly;
                uint32_t b0 = sKu[key * 68 + k0 + lx];
                uint32_t b1 = sKu[key * 68 + k0 + 4 + lx];
                mma_tf32(sacc[t], qf[kk], b0, b1);
            }
        }

        // ---- e = exp(S/8)*mask (FMA-pipe exp) ; rowsums ; stage into sA
        #pragma unroll
        for (int t = 0; t < 4; t++) {
            int gc = mt + quad * 32 + t * 8 + 2 * lx;
            float e00 = __uint_as_float(tf32r(fexp8(sacc[t][0]) * m0[t].x));
            float e01 = __uint_as_float(tf32r(fexp8(sacc[t][1]) * m0[t].y));
            float e10 = __uint_as_float(tf32r(fexp8(sacc[t][2]) * m1[t].x));
            float e11 = __uint_as_float(tf32r(fexp8(sacc[t][3]) * m1[t].y));
            rsum0 += e00 + e01;
            rsum1 += e10 + e11;
            *reinterpret_cast<float2*>(&sAf[r0 * 516 + gc]) = make_float2(e00, e01);
            *reinterpret_cast<float2*>(&sAf[r1 * 516 + gc]) = make_float2(e10, e11);
        }
        __syncthreads();   // e visible to all warps

        // ---- AV accumulate: 16 rows x 16 h-cols per warp, k over 128 keys
        #pragma unroll
        for (int k0 = 0; k0 < 128; k0 += 8) {
            uint32_t a[4];
            a[0] = sAu[r0 * 516 + mt + k0 + lx];
            a[1] = sAu[r1 * 516 + mt + k0 + lx];
            a[2] = sAu[r0 * 516 + mt + k0 + lx + 4];
            a[3] = sAu[r1 * 516 + mt + k0 + lx + 4];
            #pragma unroll
            for (int t = 0; t < 2; t++) {
                int h = quad * 16 + t * 8 + ly;
                uint32_t b0 = sVu[(k0 + lx) * 72 + h];
                uint32_t b1 = sVu[(k0 + 4 + lx) * 72 + h];
                mma_tf32(oacc[t], a, b0, b1);
            }
        }
    }

    // ---- row sums -> inverse
    rsum0 += __shfl_xor_sync(0xffffffff, rsum0, 1);
    rsum0 += __shfl_xor_sync(0xffffffff, rsum0, 2);
    rsum1 += __shfl_xor_sync(0xffffffff, rsum1, 1);
    rsum1 += __shfl_xor_sync(0xffffffff, rsum1, 2);
    if (lx == 0) {
        sm[OS + quad * 64 + r0] = rsum0;
        sm[OS + quad * 64 + r1] = rsum1;
    }
    __syncthreads();
    if (tid < 64) {
        float s = sm[OS + tid] + sm[OS + 64 + tid] + sm[OS + 128 + tid] + sm[OS + 192 + tid];
        sm[OI + tid] = (s == 0.f) ? 1.f : (1.f / s);
    }
    __syncthreads();

    // ---- write normalized A (coalesced float4)
    {
        int row = tid >> 3, s8 = tid & 7;
        float inv = sm[OI + row];
        float4* grow = reinterpret_cast<float4*>(Aout + ((size_t)b * NN + n0 + row) * NN);
        #pragma unroll
        for (int i = 0; i < 16; i++) {
            int c4 = s8 + 8 * i;
            float4 t = *reinterpret_cast<const float4*>(&sAf[row * 516 + 4 * c4]);
            t.x *= inv; t.y *= inv; t.z *= inv; t.w *= inv;
            grow[c4] = t;
        }
    }

    // ---- stage out through smem (reuse sK region), coalesced write
    {
        float* sO = sm + OK_;   // 64 x 68 fits in sK region
        float i0 = sm[OI + r0], i1 = sm[OI + r1];
        #pragma unroll
        for (int t = 0; t < 2; t++) {
            int h = quad * 16 + t * 8 + 2 * lx;
            *reinterpret_cast<float2*>(&sO[r0 * 68 + h]) =
                make_float2(oacc[t][0] * i0, oacc[t][1] * i0);
            *reinterpret_cast<float2*>(&sO[r1 * 68 + h]) =
                make_float2(oacc[t][2] * i1, oacc[t][3] * i1);
        }
        __syncthreads();
        #pragma unroll
        for (int it = 0; it < 2; it++) {
            int idx = tid + it * 512;
            int row = idx >> 4, c4 = idx & 15;
            float4 t = *reinterpret_cast<const float4*>(&sO[row * 68 + 4 * c4]);
            *reinterpret_cast<float4*>(out + ((size_t)(n0 + row) * BB + b) * HH + 4 * c4) = t;
        }
    }
}

// ---------------------------------------------------------------------------
extern "C" void kernel_launch(void* const* d_in, const int* in_sizes, int n_in,
                              void* d_out, int out_size)
{
    const float* q    = (const float*)d_in[0];
    const float* k    = (const float*)d_in[1];
    const float* v    = (const float*)d_in[2];
    const float* mask = (const float*)d_in[3];
    const float* Wq   = (const float*)d_in[4];
    const float* bq   = (const float*)d_in[5];
    const float* Wk   = (const float*)d_in[6];
    const float* bk   = (const float*)d_in[7];
    const float* Wv   = (const float*)d_in[8];
    const float* bv   = (const float*)d_in[9];

    float* out  = (float*)d_out;                         // [N,B,H] first
    float* Aout = (float*)d_out + (size_t)NN * BB * HH;  // then [B,N,N]

    const int smem_bytes = SMEM_FLOATS * 4;
    cudaFuncSetAttribute(attn_kernel, cudaFuncAttributeMaxDynamicSharedMemorySize,
                         smem_bytes);

    proj_kernel<<<dim3((NN * BB) / 128, 3), 256>>>(q, k, v, Wq, bq, Wk, bk, Wv, bv);
    attn_kernel<<<dim3(NN / 64, BB), 512, smem_bytes>>>(mask, out, Aout);
}